// round 3
// baseline (speedup 1.0000x reference)
#include <cuda_runtime.h>
#include <cstddef>

#define NN   100000
#define NE   1600000
#define DD   128
#define NLAY 7
#define NG   64
#define NCLS 10
#define SIN  512
#define SH   1024

typedef unsigned long long ull;
static const size_t NND = (size_t)NN * DD;

// ---------------- static device scratch (referenced ONLY from device code) ----------------
__device__ __align__(16) float g_h[2 * (size_t)NN * DD];   // ping-pong hidden states
__device__ __align__(16) float g_agg[(size_t)NN * DD];     // neighbor sums
__device__ int   g_deg[NN];
__device__ int   g_offs[NN];
__device__ int   g_cursor[NN];
__device__ int   g_esrc[NE];
__device__ int   g_blksum[128];
__device__ int   g_blkoff[128];
__device__ __align__(16) float g_sums[NG * DD];
__device__ float g_cnt[NG];
__device__ float g_snnlog[NG * NCLS];
__device__ int   g_is64;

// ---------------- helpers ----------------
__device__ __forceinline__ ull splat2(float x) {
    ull r;
    asm("mov.b64 %0, {%1, %1};" : "=l"(r) : "f"(x));
    return r;
}
__device__ __forceinline__ ull ffma2(ull a, ull b, ull c) {
    ull d;
    asm("fma.rn.f32x2 %0, %1, %2, %3;" : "=l"(d) : "l"(a), "l"(b), "l"(c));
    return d;
}
__device__ __forceinline__ void unpack2(ull v, float& x, float& y) {
    asm("mov.b64 {%0, %1}, %2;" : "=f"(x), "=f"(y) : "l"(v));
}
__device__ __forceinline__ float4 f4add(float4 a, float4 b) {
    return make_float4(a.x + b.x, a.y + b.y, a.z + b.z, a.w + b.w);
}
// dtype-adaptive integer read (int64 vs int32 on the wire)
__device__ __forceinline__ int geti(const void* p, size_t i, int is64) {
    return is64 ? (int)((const long long*)p)[i] : ((const int*)p)[i];
}

// ---------------- dtype detection ----------------
__global__ void k_detect(const void* ei) {
    const int* w = (const int*)ei;
    // int64 little-endian high words of nonneg small values are 0
    g_is64 = (w[1] == 0 && w[3] == 0 && w[5] == 0 && w[7] == 0) ? 1 : 0;
}

// ---------------- CSR build ----------------
__global__ void k_zero() {
    int i = blockIdx.x * blockDim.x + threadIdx.x;
    if (i < NN) g_deg[i] = 0;
    if (i < NG * DD) g_sums[i] = 0.f;
    if (i < NG) g_cnt[i] = 0.f;
}

__global__ void k_hist(const void* __restrict__ ei) {
    int e = blockIdx.x * blockDim.x + threadIdx.x;
    if (e >= NE) return;
    int dst = geti(ei, (size_t)NE + e, g_is64);
    atomicAdd(&g_deg[dst], 1);
}

__global__ void k_scan1() {
    int b = blockIdx.x, tid = threadIdx.x;
    int base = b * 1024 + tid * 4;
    int v[4]; int s = 0;
#pragma unroll
    for (int j = 0; j < 4; j++) {
        int i = base + j;
        v[j] = (i < NN) ? g_deg[i] : 0;
        s += v[j];
    }
    __shared__ int sm[256];
    int val = s;
    sm[tid] = val; __syncthreads();
    for (int off = 1; off < 256; off <<= 1) {
        int t = (tid >= off) ? sm[tid - off] : 0;
        __syncthreads();
        val += t; sm[tid] = val; __syncthreads();
    }
    int run = val - s;  // exclusive
#pragma unroll
    for (int j = 0; j < 4; j++) {
        int i = base + j;
        if (i < NN) g_offs[i] = run;
        run += v[j];
    }
    if (tid == 255) g_blksum[b] = val;
}

__global__ void k_scan2() {
    int tid = threadIdx.x;  // 128 threads
    const int NB = (NN + 1023) >> 10;
    int s = (tid < NB) ? g_blksum[tid] : 0;
    __shared__ int sm[128];
    int val = s;
    sm[tid] = val; __syncthreads();
    for (int off = 1; off < 128; off <<= 1) {
        int t = (tid >= off) ? sm[tid - off] : 0;
        __syncthreads();
        val += t; sm[tid] = val; __syncthreads();
    }
    if (tid < NB) g_blkoff[tid] = val - s;
}

__global__ void k_scan3() {
    int i = blockIdx.x * blockDim.x + threadIdx.x;
    if (i >= NN) return;
    int o = g_offs[i] + g_blkoff[i >> 10];
    g_offs[i] = o;
    g_cursor[i] = o;
}

__global__ void k_scatter(const void* __restrict__ ei) {
    int e = blockIdx.x * blockDim.x + threadIdx.x;
    if (e >= NE) return;
    int is64 = g_is64;
    int dst = geti(ei, (size_t)NE + e, is64);
    int src = geti(ei, (size_t)e, is64);
    int pos = atomicAdd(&g_cursor[dst], 1);
    g_esrc[pos] = src;
}

// ---------------- edge aggregation: warp per node, no atomics ----------------
__global__ void k_agg(const float* __restrict__ x, int layer) {
    const float* h = (layer == 0) ? x : (g_h + (size_t)((layer + 1) & 1) * NND);
    int w = (blockIdx.x * blockDim.x + threadIdx.x) >> 5;
    if (w >= NN) return;
    int lane = threadIdx.x & 31;
    int beg = g_offs[w];
    int end = (w == NN - 1) ? NE : g_offs[w + 1];
    const float4* hp = (const float4*)h;
    float4 acc0 = make_float4(0, 0, 0, 0);
    float4 acc1 = make_float4(0, 0, 0, 0);
    int e = beg;
    for (; e + 1 < end; e += 2) {
        int s0 = g_esrc[e];
        int s1 = g_esrc[e + 1];
        float4 v0 = __ldg(hp + (size_t)s0 * 32 + lane);
        float4 v1 = __ldg(hp + (size_t)s1 * 32 + lane);
        acc0 = f4add(acc0, v0);
        acc1 = f4add(acc1, v1);
    }
    if (e < end) {
        acc0 = f4add(acc0, __ldg(hp + (size_t)g_esrc[e] * 32 + lane));
    }
    acc0 = f4add(acc0, acc1);
    ((float4*)(g_agg + (size_t)w * DD))[lane] = acc0;
}

// ---------------- fused conv GEMM: out = relu([agg|h] @ [Wrel;Wroot] + brel) ----------------
// 128x128 tile, K=256 in 16 chunks of 16, static smem (<48KB), f32x2 packed FMA.
__global__ void __launch_bounds__(256, 2)
k_conv(const float* __restrict__ x,
       const float* __restrict__ wrel,
       const float* __restrict__ wroot,
       const float* __restrict__ bias,
       int layer) {
    __shared__ __align__(16) float As[2][16][132];   // k-major A chunk
    __shared__ __align__(16) float Bs[2][16][128];   // B chunk

    const float* A2 = (layer == 0) ? x : (g_h + (size_t)((layer + 1) & 1) * NND);
    float* out = g_h + (size_t)(layer & 1) * NND;
    const float* A1 = g_agg;

    int tid = threadIdx.x;
    int m0 = blockIdx.x * 128;

    int arow = tid >> 1;           // 0..127
    int acol = (tid & 1) * 8;      // 0 or 8 (k within chunk)
    int ty = tid >> 4;             // 0..15: rows ty*8..+7
    int tx = tid & 15;             // 0..15: cols tx*4..+3 and 64+tx*4..+3

    float4 ra0, ra1, rb0, rb1;

    auto gload = [&](int kc) {
        const float* Asrc = (kc < 8) ? A1 : A2;
        int kb = (kc & 7) * 16;
        int rg = m0 + arow;
        if (rg < NN) {
            const float* p = Asrc + (size_t)rg * DD + kb + acol;
            ra0 = *(const float4*)p;
            ra1 = *(const float4*)(p + 4);
        } else {
            ra0 = make_float4(0, 0, 0, 0);
            ra1 = ra0;
        }
        const float* Bsrc = (kc < 8) ? wrel : wroot;
        const float4* bp = (const float4*)(Bsrc + (size_t)(kc & 7) * 16 * 128);
        rb0 = bp[tid];
        rb1 = bp[tid + 256];
    };
    auto sstore = [&](int buf) {
        As[buf][acol + 0][arow] = ra0.x;
        As[buf][acol + 1][arow] = ra0.y;
        As[buf][acol + 2][arow] = ra0.z;
        As[buf][acol + 3][arow] = ra0.w;
        As[buf][acol + 4][arow] = ra1.x;
        As[buf][acol + 5][arow] = ra1.y;
        As[buf][acol + 6][arow] = ra1.z;
        As[buf][acol + 7][arow] = ra1.w;
        ((float4*)&Bs[buf][0][0])[tid] = rb0;
        ((float4*)&Bs[buf][0][0])[tid + 256] = rb1;
    };

    gload(0);
    sstore(0);
    __syncthreads();

    ull acc[8][4];
#pragma unroll
    for (int r = 0; r < 8; r++)
#pragma unroll
        for (int c = 0; c < 4; c++) acc[r][c] = 0ULL;

    for (int kc = 0; kc < 16; kc++) {
        int buf = kc & 1;
        if (kc < 15) gload(kc + 1);
#pragma unroll
        for (int k = 0; k < 16; k++) {
            float4 a0 = *(const float4*)&As[buf][k][ty * 8];
            float4 a1 = *(const float4*)&As[buf][k][ty * 8 + 4];
            ull av[8];
            av[0] = splat2(a0.x); av[1] = splat2(a0.y);
            av[2] = splat2(a0.z); av[3] = splat2(a0.w);
            av[4] = splat2(a1.x); av[5] = splat2(a1.y);
            av[6] = splat2(a1.z); av[7] = splat2(a1.w);
            longlong2 b0 = *(const longlong2*)&Bs[buf][k][tx * 4];
            longlong2 b1 = *(const longlong2*)&Bs[buf][k][64 + tx * 4];
            ull bv[4];
            bv[0] = (ull)b0.x; bv[1] = (ull)b0.y;
            bv[2] = (ull)b1.x; bv[3] = (ull)b1.y;
#pragma unroll
            for (int r = 0; r < 8; r++)
#pragma unroll
                for (int c = 0; c < 4; c++)
                    acc[r][c] = ffma2(av[r], bv[c], acc[r][c]);
        }
        __syncthreads();
        if (kc < 15) {
            sstore(buf ^ 1);
            __syncthreads();
        }
    }

    // epilogue: bias + relu + store
    float4 bc0 = __ldg((const float4*)(bias + tx * 4));
    float4 bc1 = __ldg((const float4*)(bias + 64 + tx * 4));
#pragma unroll
    for (int r = 0; r < 8; r++) {
        int row = m0 + ty * 8 + r;
        if (row >= NN) break;
        float v[8];
        unpack2(acc[r][0], v[0], v[1]);
        unpack2(acc[r][1], v[2], v[3]);
        unpack2(acc[r][2], v[4], v[5]);
        unpack2(acc[r][3], v[6], v[7]);
        float4 o0 = make_float4(fmaxf(v[0] + bc0.x, 0.f), fmaxf(v[1] + bc0.y, 0.f),
                                fmaxf(v[2] + bc0.z, 0.f), fmaxf(v[3] + bc0.w, 0.f));
        float4 o1 = make_float4(fmaxf(v[4] + bc1.x, 0.f), fmaxf(v[5] + bc1.y, 0.f),
                                fmaxf(v[6] + bc1.z, 0.f), fmaxf(v[7] + bc1.w, 0.f));
        *(float4*)(out + (size_t)row * DD + tx * 4) = o0;
        *(float4*)(out + (size_t)row * DD + 64 + tx * 4) = o1;
    }
}

// ---------------- mean pool: warp per 64-node chunk, batch is sorted ----------------
#define PCH 64
__global__ void k_pool(const void* __restrict__ batch) {
    const float* h = g_h;  // layer 6 output lives in buffer 0
    int w = (blockIdx.x * blockDim.x + threadIdx.x) >> 5;
    int lane = threadIdx.x & 31;
    int n0 = w * PCH;
    if (n0 >= NN) return;
    int n1 = n0 + PCH; if (n1 > NN) n1 = NN;
    int is64 = g_is64;
    const float4* hp = (const float4*)h;
    float4 acc = make_float4(0, 0, 0, 0);
    int g = geti(batch, (size_t)n0, is64);
    int cnt = 0;
    for (int n = n0; n < n1; n++) {
        int gn = geti(batch, (size_t)n, is64);
        if (gn != g) {
            float* sp = g_sums + g * DD + lane * 4;
            atomicAdd(sp + 0, acc.x); atomicAdd(sp + 1, acc.y);
            atomicAdd(sp + 2, acc.z); atomicAdd(sp + 3, acc.w);
            if (lane == 0) atomicAdd(&g_cnt[g], (float)cnt);
            acc = make_float4(0, 0, 0, 0); cnt = 0; g = gn;
        }
        acc = f4add(acc, __ldg(hp + (size_t)n * 32 + lane));
        cnt++;
    }
    float* sp = g_sums + g * DD + lane * 4;
    atomicAdd(sp + 0, acc.x); atomicAdd(sp + 1, acc.y);
    atomicAdd(sp + 2, acc.z); atomicAdd(sp + 3, acc.w);
    if (lane == 0) atomicAdd(&g_cnt[g], (float)cnt);
}

// ---------------- SNN branch: block per graph row ----------------
__global__ void k_snn(const float* __restrict__ x, const float* __restrict__ w1,
                      const float* __restrict__ b1, const float* __restrict__ w2,
                      const float* __restrict__ b2) {
    int g = blockIdx.x, tid = threadIdx.x;
    __shared__ float xs[SIN];
    __shared__ float hs[SH];
    __shared__ float rd[256];
    for (int i = tid; i < SIN; i += 256) xs[i] = x[g * SIN + i];
    __syncthreads();
    float a0 = 0, a1 = 0, a2 = 0, a3 = 0;
    for (int k = 0; k < SIN; k++) {
        float xv = xs[k];
        const float* wr = w1 + (size_t)k * SH + tid;
        a0 += xv * __ldg(wr + 0);
        a1 += xv * __ldg(wr + 256);
        a2 += xv * __ldg(wr + 512);
        a3 += xv * __ldg(wr + 768);
    }
    hs[tid + 0]   = fmaxf(a0 + b1[tid + 0],   0.f);
    hs[tid + 256] = fmaxf(a1 + b1[tid + 256], 0.f);
    hs[tid + 512] = fmaxf(a2 + b1[tid + 512], 0.f);
    hs[tid + 768] = fmaxf(a3 + b1[tid + 768], 0.f);
    __syncthreads();
    float p[NCLS];
#pragma unroll
    for (int c = 0; c < NCLS; c++) p[c] = 0.f;
    for (int k = tid; k < SH; k += 256) {
        float hv = hs[k];
#pragma unroll
        for (int c = 0; c < NCLS; c++) p[c] += hv * __ldg(w2 + k * NCLS + c);
    }
    for (int c = 0; c < NCLS; c++) {
        rd[tid] = p[c]; __syncthreads();
        for (int s = 128; s > 0; s >>= 1) {
            if (tid < s) rd[tid] += rd[tid + s];
            __syncthreads();
        }
        if (tid == 0) g_snnlog[g * NCLS + c] = 0.85f * (rd[0] + b2[c]);
        __syncthreads();
    }
}

// ---------------- pooled finish + gnn logits + fusion ----------------
__global__ void k_fuse(const float* __restrict__ lin_w, const float* __restrict__ lin_b,
                       const float* __restrict__ fw, const float* __restrict__ fb,
                       float* __restrict__ out) {
    int g = blockIdx.x, tid = threadIdx.x;  // 128 threads
    __shared__ float pp[DD];
    __shared__ float cat[2 * NCLS];
    float c = fmaxf(g_cnt[g], 1.f);
    pp[tid] = g_sums[g * DD + tid] / c;
    __syncthreads();
    if (tid < NCLS) {
        float s = lin_b[tid];
        for (int d = 0; d < DD; d++) s += pp[d] * lin_w[d * NCLS + tid];
        cat[NCLS + tid] = s;
        cat[tid] = g_snnlog[g * NCLS + tid];
    }
    __syncthreads();
    if (tid < NCLS) {
        float s = fb[tid];
#pragma unroll
        for (int j = 0; j < 2 * NCLS; j++) s += cat[j] * fw[j * NCLS + tid];
        out[g * NCLS + tid] = s;
    }
}

// ---------------- host launcher: kernel launches ONLY ----------------
extern "C" void kernel_launch(void* const* d_in, const int* in_sizes, int n_in,
                              void* d_out, int out_size) {
    const float* snn_x  = (const float*)d_in[0];
    const float* x      = (const float*)d_in[1];
    const void*  ei     = d_in[2];
    const void*  batch  = d_in[3];
    const float* w1     = (const float*)d_in[4];
    const float* b1     = (const float*)d_in[5];
    const float* w2     = (const float*)d_in[6];
    const float* b2     = (const float*)d_in[7];
    const float* cwrel  = (const float*)d_in[8];
    const float* cwroot = (const float*)d_in[9];
    const float* cbrel  = (const float*)d_in[10];
    const float* lin_w  = (const float*)d_in[11];
    const float* lin_b  = (const float*)d_in[12];
    const float* fw     = (const float*)d_in[13];
    const float* fb     = (const float*)d_in[14];
    float* out = (float*)d_out;

    k_detect<<<1, 1>>>(ei);

    // CSR build (dst-sorted edge list, reused by all 7 layers)
    k_zero<<<(NN + 255) / 256, 256>>>();
    k_hist<<<(NE + 255) / 256, 256>>>(ei);
    k_scan1<<<(NN + 1023) / 1024, 256>>>();
    k_scan2<<<1, 128>>>();
    k_scan3<<<(NN + 255) / 256, 256>>>();
    k_scatter<<<(NE + 255) / 256, 256>>>(ei);

    // SNN branch (independent)
    k_snn<<<NG, 256>>>(snn_x, w1, b1, w2, b2);

    // 7 GraphConv layers
    for (int l = 0; l < NLAY; l++) {
        k_agg<<<(NN * 32 + 255) / 256, 256>>>(x, l);
        k_conv<<<(NN + 127) / 128, 256>>>(
            x,
            cwrel + (size_t)l * DD * DD,
            cwroot + (size_t)l * DD * DD,
            cbrel + (size_t)l * DD,
            l);
    }

    // pool + fuse
    k_pool<<<(((NN + PCH - 1) / PCH) * 32 + 255) / 256, 256>>>(batch);
    k_fuse<<<NG, 128>>>(lin_w, lin_b, fw, fb, out);
}

// round 5
// speedup vs baseline: 1.3237x; 1.3237x over previous
#include <cuda_runtime.h>
#include <cuda_bf16.h>
#include <cstddef>
#include <cstdint>

#define NN   100000
#define NE   1600000
#define DD   128
#define NLAY 7
#define NG   64
#define NCLS 10
#define SIN  512
#define SH   1024

typedef unsigned long long ull;
typedef unsigned int uint;
static const size_t NND = (size_t)NN * DD;

// ---------------- static device scratch (referenced ONLY from device code) ----------------
__device__ __align__(16) float g_h[2 * (size_t)NN * DD];   // ping-pong hidden states
__device__ __align__(16) float g_agg[(size_t)NN * DD];     // neighbor sums
__device__ int   g_deg[NN];
__device__ int   g_offs[NN];
__device__ int   g_cursor[NN];
__device__ int   g_esrc[NE];
__device__ int   g_blksum[128];
__device__ int   g_blkoff[128];
__device__ __align__(16) float g_sums[NG * DD];
__device__ float g_cnt[NG];
__device__ float g_snnlog[NG * NCLS];
__device__ int   g_is64;
// bf16 hi/lo weights, B^T layout: [layer][v=hi/lo][n=128][k=256]
__device__ __align__(16) __nv_bfloat16 g_wb[(size_t)NLAY * 2 * 128 * 256];

// ---------------- helpers ----------------
__device__ __forceinline__ float4 f4add(float4 a, float4 b) {
    return make_float4(a.x + b.x, a.y + b.y, a.z + b.z, a.w + b.w);
}
__device__ __forceinline__ int geti(const void* p, size_t i, int is64) {
    return is64 ? (int)((const long long*)p)[i] : ((const int*)p)[i];
}
__device__ __forceinline__ uint smem_u32(const void* p) {
    uint a;
    asm("{ .reg .u64 t; cvta.to.shared.u64 t, %1; cvt.u32.u64 %0, t; }" : "=r"(a) : "l"(p));
    return a;
}
__device__ __forceinline__ void ldsm4(uint* r, uint addr) {
    asm volatile("ldmatrix.sync.aligned.m8n8.x4.shared.b16 {%0,%1,%2,%3}, [%4];"
                 : "=r"(r[0]), "=r"(r[1]), "=r"(r[2]), "=r"(r[3]) : "r"(addr));
}
__device__ __forceinline__ void mma16816(float* c, const uint* a, uint b0, uint b1) {
    asm volatile(
        "mma.sync.aligned.m16n8k16.row.col.f32.bf16.bf16.f32 "
        "{%0,%1,%2,%3}, {%4,%5,%6,%7}, {%8,%9}, {%0,%1,%2,%3};"
        : "+f"(c[0]), "+f"(c[1]), "+f"(c[2]), "+f"(c[3])
        : "r"(a[0]), "r"(a[1]), "r"(a[2]), "r"(a[3]), "r"(b0), "r"(b1));
}
__device__ __forceinline__ uint bf2u(__nv_bfloat162 v) { return *(uint*)&v; }

// ---------------- dtype detection ----------------
__global__ void k_detect(const void* ei) {
    const int* w = (const int*)ei;
    g_is64 = (w[1] == 0 && w[3] == 0 && w[5] == 0 && w[7] == 0) ? 1 : 0;
}

// ---------------- CSR build ----------------
__global__ void k_zero() {
    int i = blockIdx.x * blockDim.x + threadIdx.x;
    if (i < NN) g_deg[i] = 0;
    if (i < NG * DD) g_sums[i] = 0.f;
    if (i < NG) g_cnt[i] = 0.f;
}

__global__ void k_hist(const void* __restrict__ ei) {
    int e = blockIdx.x * blockDim.x + threadIdx.x;
    if (e >= NE) return;
    atomicAdd(&g_deg[geti(ei, (size_t)NE + e, g_is64)], 1);
}

__global__ void k_scan1() {
    int b = blockIdx.x, tid = threadIdx.x;
    int base = b * 1024 + tid * 4;
    int v[4]; int s = 0;
#pragma unroll
    for (int j = 0; j < 4; j++) {
        int i = base + j;
        v[j] = (i < NN) ? g_deg[i] : 0;
        s += v[j];
    }
    __shared__ int sm[256];
    int val = s;
    sm[tid] = val; __syncthreads();
    for (int off = 1; off < 256; off <<= 1) {
        int t = (tid >= off) ? sm[tid - off] : 0;
        __syncthreads();
        val += t; sm[tid] = val; __syncthreads();
    }
    int run = val - s;
#pragma unroll
    for (int j = 0; j < 4; j++) {
        int i = base + j;
        if (i < NN) g_offs[i] = run;
        run += v[j];
    }
    if (tid == 255) g_blksum[b] = val;
}

__global__ void k_scan2() {
    int tid = threadIdx.x;
    const int NB = (NN + 1023) >> 10;
    int s = (tid < NB) ? g_blksum[tid] : 0;
    __shared__ int sm[128];
    int val = s;
    sm[tid] = val; __syncthreads();
    for (int off = 1; off < 128; off <<= 1) {
        int t = (tid >= off) ? sm[tid - off] : 0;
        __syncthreads();
        val += t; sm[tid] = val; __syncthreads();
    }
    if (tid < NB) g_blkoff[tid] = val - s;
}

__global__ void k_scan3() {
    int i = blockIdx.x * blockDim.x + threadIdx.x;
    if (i >= NN) return;
    int o = g_offs[i] + g_blkoff[i >> 10];
    g_offs[i] = o;
    g_cursor[i] = o;
}

__global__ void k_scatter(const void* __restrict__ ei) {
    int e = blockIdx.x * blockDim.x + threadIdx.x;
    if (e >= NE) return;
    int is64 = g_is64;
    int dst = geti(ei, (size_t)NE + e, is64);
    int src = geti(ei, (size_t)e, is64);
    int pos = atomicAdd(&g_cursor[dst], 1);
    g_esrc[pos] = src;
}

// ---------------- weight prep: fp32 W -> B^T bf16 hi/lo [n][k256] ----------------
__global__ void k_prepw(const float* __restrict__ wrel, const float* __restrict__ wroot) {
    int bid = blockIdx.x;      // NLAY*2
    int v = bid & 1, l = bid >> 1;
    const float* Wr = wrel + (size_t)l * DD * DD;
    const float* Wo = wroot + (size_t)l * DD * DD;
    __nv_bfloat16* dst = g_wb + (size_t)(l * 2 + v) * 128 * 256;
    int t = threadIdx.x;           // 256 threads
    int n = t >> 1;
    int kh = (t & 1) * 128;
#pragma unroll 4
    for (int k = 0; k < 128; k++) {
        int kg = kh + k;
        float w = (kg < 128) ? Wr[(size_t)kg * DD + n] : Wo[(size_t)(kg - 128) * DD + n];
        __nv_bfloat16 hi = __float2bfloat16_rn(w);
        __nv_bfloat16 o = v ? __float2bfloat16_rn(w - __bfloat162float(hi)) : hi;
        dst[(size_t)n * 256 + kg] = o;
    }
}

// ---------------- edge aggregation: warp per node, no atomics ----------------
__global__ void k_agg(const float* __restrict__ x, int layer) {
    const float* h = (layer == 0) ? x : (g_h + (size_t)((layer + 1) & 1) * NND);
    int w = (blockIdx.x * blockDim.x + threadIdx.x) >> 5;
    if (w >= NN) return;
    int lane = threadIdx.x & 31;
    int beg = g_offs[w];
    int end = (w == NN - 1) ? NE : g_offs[w + 1];
    const float4* hp = (const float4*)h;
    float4 acc0 = make_float4(0, 0, 0, 0);
    float4 acc1 = make_float4(0, 0, 0, 0);
    int e = beg;
    for (; e + 1 < end; e += 2) {
        int s0 = g_esrc[e];
        int s1 = g_esrc[e + 1];
        float4 v0 = __ldg(hp + (size_t)s0 * 32 + lane);
        float4 v1 = __ldg(hp + (size_t)s1 * 32 + lane);
        acc0 = f4add(acc0, v0);
        acc1 = f4add(acc1, v1);
    }
    if (e < end) acc0 = f4add(acc0, __ldg(hp + (size_t)g_esrc[e] * 32 + lane));
    acc0 = f4add(acc0, acc1);
    ((float4*)(g_agg + (size_t)w * DD))[lane] = acc0;
}

// ---------------- HMMA conv GEMM: out = relu([agg|h] @ [Wrel;Wroot] + b) ----------------
// 128x128 CTA tile, 8 warps (warp tile 32x64), K=256 in 8 chunks of 32,
// 3-term bf16 split via mma.sync.m16n8k16, fp32 accum in regs.
__global__ void __launch_bounds__(256)
k_conv_hmma(const float* __restrict__ x, const float* __restrict__ bias, int layer) {
    __shared__ __align__(16) __nv_bfloat16 sAh[128][40];
    __shared__ __align__(16) __nv_bfloat16 sAl[128][40];
    __shared__ __align__(16) __nv_bfloat16 sBh[128][40];
    __shared__ __align__(16) __nv_bfloat16 sBl[128][40];
    __shared__ float s_bias[128];

    const float* hprev = (layer == 0) ? x : (g_h + (size_t)((layer + 1) & 1) * NND);
    float* out = g_h + (size_t)(layer & 1) * NND;
    const __nv_bfloat16* wb = g_wb + (size_t)layer * 2 * 128 * 256;

    int tid = threadIdx.x, lane = tid & 31, wid = tid >> 5;
    int m0 = blockIdx.x * 128;
    int warp_m = wid & 3, warp_n = wid >> 2;

    if (tid < 128) s_bias[tid] = bias[tid];

    // per-thread staging coordinates
    int arow = tid >> 1;
    int aks  = (tid & 1) * 16;
    int brow = tid >> 1;
    int bseg = (tid & 1) * 16;

    float4 pa[4];
    uint4 pbh[2], pbl[2];

    auto loadG = [&](int kc) {
        int kg = kc * 32;
        const float* Asrc = (kg < 128) ? g_agg : hprev;
        int kb = kg & 127;
        int rg = m0 + arow;
        if (rg < NN) {
            const float* p = Asrc + (size_t)rg * DD + kb + aks;
            pa[0] = __ldg((const float4*)p);
            pa[1] = __ldg((const float4*)(p + 4));
            pa[2] = __ldg((const float4*)(p + 8));
            pa[3] = __ldg((const float4*)(p + 12));
        } else {
            pa[0] = make_float4(0, 0, 0, 0);
            pa[1] = pa[0]; pa[2] = pa[0]; pa[3] = pa[0];
        }
        const uint4* bh = (const uint4*)(wb + (size_t)brow * 256 + kg + bseg);
        pbh[0] = __ldg(bh); pbh[1] = __ldg(bh + 1);
        const uint4* bl = (const uint4*)(wb + (size_t)(128 + brow) * 256 + kg + bseg);
        pbl[0] = __ldg(bl); pbl[1] = __ldg(bl + 1);
    };

    auto storeS = [&]() {
#pragma unroll
        for (int q = 0; q < 4; q++) {
            float4 v = pa[q];
            __nv_bfloat162 h0 = __floats2bfloat162_rn(v.x, v.y);
            __nv_bfloat162 h1 = __floats2bfloat162_rn(v.z, v.w);
            __nv_bfloat162 l0 = __floats2bfloat162_rn(v.x - __low2float(h0), v.y - __high2float(h0));
            __nv_bfloat162 l1 = __floats2bfloat162_rn(v.z - __low2float(h1), v.w - __high2float(h1));
            *(uint*)&sAh[arow][aks + q * 4]     = bf2u(h0);
            *(uint*)&sAh[arow][aks + q * 4 + 2] = bf2u(h1);
            *(uint*)&sAl[arow][aks + q * 4]     = bf2u(l0);
            *(uint*)&sAl[arow][aks + q * 4 + 2] = bf2u(l1);
        }
        *(uint4*)&sBh[brow][bseg]     = pbh[0];
        *(uint4*)&sBh[brow][bseg + 8] = pbh[1];
        *(uint4*)&sBl[brow][bseg]     = pbl[0];
        *(uint4*)&sBl[brow][bseg + 8] = pbl[1];
    };

    // ldmatrix byte offsets (same within each of the 4 smem arrays)
    uint sAh_u = smem_u32(&sAh[0][0]);
    uint sAl_u = smem_u32(&sAl[0][0]);
    uint sBh_u = smem_u32(&sBh[0][0]);
    uint sBl_u = smem_u32(&sBl[0][0]);
    int row_a = warp_m * 32 + (lane & 15);
    int col8a = (lane >> 4) * 8;
    uint aoff0 = (uint)(row_a * 80 + col8a * 2);
    uint aoff1 = (uint)((row_a + 16) * 80 + col8a * 2);
    int row_b = warp_n * 64 + (lane & 7) + ((lane & 16) ? 8 : 0);
    int col8b = (lane & 8) ? 8 : 0;
    uint boff = (uint)(row_b * 80 + col8b * 2);

    float acc[2][8][4];
#pragma unroll
    for (int mt = 0; mt < 2; mt++)
#pragma unroll
        for (int nf = 0; nf < 8; nf++)
#pragma unroll
            for (int q = 0; q < 4; q++) acc[mt][nf][q] = 0.f;

    auto pass = [&](uint sAu, uint sBu) {
#pragma unroll
        for (int k16 = 0; k16 < 2; k16++) {
            uint a0[4], a1[4];
            ldsm4(a0, sAu + aoff0 + k16 * 32);
            ldsm4(a1, sAu + aoff1 + k16 * 32);
#pragma unroll
            for (int g = 0; g < 4; g++) {
                uint b[4];
                ldsm4(b, sBu + boff + (uint)g * 1280 + k16 * 32);
                mma16816(acc[0][2 * g],     a0, b[0], b[1]);
                mma16816(acc[0][2 * g + 1], a0, b[2], b[3]);
                mma16816(acc[1][2 * g],     a1, b[0], b[1]);
                mma16816(acc[1][2 * g + 1], a1, b[2], b[3]);
            }
        }
    };

    loadG(0);
    for (int kc = 0; kc < 8; kc++) {
        __syncthreads();
        storeS();
        __syncthreads();
        if (kc < 7) loadG(kc + 1);
        pass(sAh_u, sBh_u);   // Ah*Bh
        pass(sAl_u, sBh_u);   // Al*Bh
        pass(sAh_u, sBl_u);   // Ah*Bl
    }

    // epilogue: bias + relu + store
    int crow = lane >> 2;
    int ccol = (lane & 3) * 2;
#pragma unroll
    for (int mt = 0; mt < 2; mt++) {
#pragma unroll
        for (int nf = 0; nf < 8; nf++) {
            int col = warp_n * 64 + nf * 8 + ccol;
            float b0 = s_bias[col], b1 = s_bias[col + 1];
            int row0 = m0 + warp_m * 32 + mt * 16 + crow;
            if (row0 < NN) {
                float2 o;
                o.x = fmaxf(acc[mt][nf][0] + b0, 0.f);
                o.y = fmaxf(acc[mt][nf][1] + b1, 0.f);
                *(float2*)(out + (size_t)row0 * DD + col) = o;
            }
            if (row0 + 8 < NN) {
                float2 o;
                o.x = fmaxf(acc[mt][nf][2] + b0, 0.f);
                o.y = fmaxf(acc[mt][nf][3] + b1, 0.f);
                *(float2*)(out + (size_t)(row0 + 8) * DD + col) = o;
            }
        }
    }
}

// ---------------- mean pool ----------------
#define PCH 64
__global__ void k_pool(const void* __restrict__ batch) {
    const float* h = g_h;  // layer 6 output in buffer 0
    int w = (blockIdx.x * blockDim.x + threadIdx.x) >> 5;
    int lane = threadIdx.x & 31;
    int n0 = w * PCH;
    if (n0 >= NN) return;
    int n1 = n0 + PCH; if (n1 > NN) n1 = NN;
    int is64 = g_is64;
    const float4* hp = (const float4*)h;
    float4 acc = make_float4(0, 0, 0, 0);
    int g = geti(batch, (size_t)n0, is64);
    int cnt = 0;
    for (int n = n0; n < n1; n++) {
        int gn = geti(batch, (size_t)n, is64);
        if (gn != g) {
            float* sp = g_sums + g * DD + lane * 4;
            atomicAdd(sp + 0, acc.x); atomicAdd(sp + 1, acc.y);
            atomicAdd(sp + 2, acc.z); atomicAdd(sp + 3, acc.w);
            if (lane == 0) atomicAdd(&g_cnt[g], (float)cnt);
            acc = make_float4(0, 0, 0, 0); cnt = 0; g = gn;
        }
        acc = f4add(acc, __ldg(hp + (size_t)n * 32 + lane));
        cnt++;
    }
    float* sp = g_sums + g * DD + lane * 4;
    atomicAdd(sp + 0, acc.x); atomicAdd(sp + 1, acc.y);
    atomicAdd(sp + 2, acc.z); atomicAdd(sp + 3, acc.w);
    if (lane == 0) atomicAdd(&g_cnt[g], (float)cnt);
}

// ---------------- SNN branch ----------------
__global__ void k_snn(const float* __restrict__ x, const float* __restrict__ w1,
                      const float* __restrict__ b1, const float* __restrict__ w2,
                      const float* __restrict__ b2) {
    int g = blockIdx.x, tid = threadIdx.x;
    __shared__ float xs[SIN];
    __shared__ float hs[SH];
    __shared__ float rd[256];
    for (int i = tid; i < SIN; i += 256) xs[i] = x[g * SIN + i];
    __syncthreads();
    float a0 = 0, a1 = 0, a2 = 0, a3 = 0;
    for (int k = 0; k < SIN; k++) {
        float xv = xs[k];
        const float* wr = w1 + (size_t)k * SH + tid;
        a0 += xv * __ldg(wr + 0);
        a1 += xv * __ldg(wr + 256);
        a2 += xv * __ldg(wr + 512);
        a3 += xv * __ldg(wr + 768);
    }
    hs[tid + 0]   = fmaxf(a0 + b1[tid + 0],   0.f);
    hs[tid + 256] = fmaxf(a1 + b1[tid + 256], 0.f);
    hs[tid + 512] = fmaxf(a2 + b1[tid + 512], 0.f);
    hs[tid + 768] = fmaxf(a3 + b1[tid + 768], 0.f);
    __syncthreads();
    float p[NCLS];
#pragma unroll
    for (int c = 0; c < NCLS; c++) p[c] = 0.f;
    for (int k = tid; k < SH; k += 256) {
        float hv = hs[k];
#pragma unroll
        for (int c = 0; c < NCLS; c++) p[c] += hv * __ldg(w2 + k * NCLS + c);
    }
    for (int c = 0; c < NCLS; c++) {
        rd[tid] = p[c]; __syncthreads();
        for (int s = 128; s > 0; s >>= 1) {
            if (tid < s) rd[tid] += rd[tid + s];
            __syncthreads();
        }
        if (tid == 0) g_snnlog[g * NCLS + c] = 0.85f * (rd[0] + b2[c]);
        __syncthreads();
    }
}

// ---------------- fusion ----------------
__global__ void k_fuse(const float* __restrict__ lin_w, const float* __restrict__ lin_b,
                       const float* __restrict__ fw, const float* __restrict__ fb,
                       float* __restrict__ out) {
    int g = blockIdx.x, tid = threadIdx.x;
    __shared__ float pp[DD];
    __shared__ float cat[2 * NCLS];
    float c = fmaxf(g_cnt[g], 1.f);
    pp[tid] = g_sums[g * DD + tid] / c;
    __syncthreads();
    if (tid < NCLS) {
        float s = lin_b[tid];
        for (int d = 0; d < DD; d++) s += pp[d] * lin_w[d * NCLS + tid];
        cat[NCLS + tid] = s;
        cat[tid] = g_snnlog[g * NCLS + tid];
    }
    __syncthreads();
    if (tid < NCLS) {
        float s = fb[tid];
#pragma unroll
        for (int j = 0; j < 2 * NCLS; j++) s += cat[j] * fw[j * NCLS + tid];
        out[g * NCLS + tid] = s;
    }
}

// ---------------- host launcher: kernel launches ONLY ----------------
extern "C" void kernel_launch(void* const* d_in, const int* in_sizes, int n_in,
                              void* d_out, int out_size) {
    const float* snn_x  = (const float*)d_in[0];
    const float* x      = (const float*)d_in[1];
    const void*  ei     = d_in[2];
    const void*  batch  = d_in[3];
    const float* w1     = (const float*)d_in[4];
    const float* b1     = (const float*)d_in[5];
    const float* w2     = (const float*)d_in[6];
    const float* b2     = (const float*)d_in[7];
    const float* cwrel  = (const float*)d_in[8];
    const float* cwroot = (const float*)d_in[9];
    const float* cbrel  = (const float*)d_in[10];
    const float* lin_w  = (const float*)d_in[11];
    const float* lin_b  = (const float*)d_in[12];
    const float* fw     = (const float*)d_in[13];
    const float* fb     = (const float*)d_in[14];
    float* out = (float*)d_out;

    k_detect<<<1, 1>>>(ei);

    // CSR build (dst-sorted edge list, reused by all 7 layers)
    k_zero<<<(NN + 255) / 256, 256>>>();
    k_hist<<<(NE + 255) / 256, 256>>>(ei);
    k_scan1<<<(NN + 1023) / 1024, 256>>>();
    k_scan2<<<1, 128>>>();
    k_scan3<<<(NN + 255) / 256, 256>>>();
    k_scatter<<<(NE + 255) / 256, 256>>>(ei);

    // weight prep (bf16 hi/lo, B^T layout)
    k_prepw<<<NLAY * 2, 256>>>(cwrel, cwroot);

    // SNN branch (independent)
    k_snn<<<NG, 256>>>(snn_x, w1, b1, w2, b2);

    // 7 GraphConv layers
    for (int l = 0; l < NLAY; l++) {
        k_agg<<<(NN * 32 + 255) / 256, 256>>>(x, l);
        k_conv_hmma<<<(NN + 127) / 128, 256>>>(x, cbrel + (size_t)l * DD, l);
    }

    // pool + fuse
    k_pool<<<(((NN + PCH - 1) / PCH) * 32 + 255) / 256, 256>>>(batch);
    k_fuse<<<NG, 128>>>(lin_w, lin_b, fw, fb, out);
}